// round 5
// baseline (speedup 1.0000x reference)
#include <cuda_runtime.h>
#include <cuda_bf16.h>

// Shapes (fixed)
#define B_   32
#define P_   16
#define S_   256
#define D_   256
#define NG_  128
#define N_   4096
#define E_   65536
#define H_   256

#define NBLK 128
#define NTHR 1024

// ---------------- scratch ----------------------------------------------------
__device__ __align__(16) float g_node_x[N_ * D_];
__device__ float g_dis[N_];
__device__ int   g_cnt[N_];
__device__ int   g_cursor[N_];
__device__ int   g_offs[N_ + 1];
__device__ __align__(16) int   g_csr_src[E_];
__device__ __align__(16) float g_csr_w[E_];
__device__ __align__(16) float g_agg[N_ * D_];
__device__ __align__(16) float g_x1[N_ * H_];
__device__ float g_C[N_ * B_];
__device__ __align__(16) float g_part[NBLK * 4 * B_ * H_];   // 512 slots x 8192
__device__ float g_tmp[B_ * H_];

// grid barrier state (zero-init at module load; self-restoring across launches)
__device__ unsigned g_barcnt;
__device__ unsigned g_barrel;

__device__ __forceinline__ void gbar(unsigned gen0, unsigned k) {
    __syncthreads();
    if (threadIdx.x == 0) {
        __threadfence();
        unsigned a = atomicAdd(&g_barcnt, 1u);
        if (a == NBLK - 1u) {
            g_barcnt = 0;
            __threadfence();
            atomicAdd(&g_barrel, 1u);
        } else {
            for (long long it = 0; it < 50000000LL; ++it) {   // bounded: never hang
                unsigned cur = *(volatile unsigned*)&g_barrel;
                if (cur - gen0 >= k) break;
                __nanosleep(32);
            }
        }
        __threadfence();
    }
    __syncthreads();
}

// packed fp32x2 helpers
__device__ __forceinline__ unsigned long long ffma2(unsigned long long a,
                                                    unsigned long long b,
                                                    unsigned long long c) {
    unsigned long long d;
    asm("fma.rn.f32x2 %0, %1, %2, %3;" : "=l"(d) : "l"(a), "l"(b), "l"(c));
    return d;
}
__device__ __forceinline__ unsigned long long pk2(float x) {
    unsigned long long r; unsigned u = __float_as_uint(x);
    asm("mov.b64 %0, {%1, %2};" : "=l"(r) : "r"(u), "r"(u));
    return r;
}

__global__ void __launch_bounds__(NTHR)
fused_kernel(const float* __restrict__ dge, const int* __restrict__ gids,
             const int* __restrict__ ei,
             const float* __restrict__ W1, const float* __restrict__ b1,
             const float* __restrict__ W2, const float* __restrict__ b2,
             float* __restrict__ out) {
    const int tid = threadIdx.x;
    const int bid = blockIdx.x;
    const int idx = bid * NTHR + tid;    // 0..131071

    unsigned gen0 = 0;
    if (tid == 0) gen0 = *(volatile unsigned*)&g_barrel;

    __shared__ __align__(16) int   s_scan[NTHR];
    __shared__ __align__(16) float sC[32][33];
    __shared__ __align__(16) float As[16][132];   // [k][m], stride 528B
    __shared__ __align__(16) float Bs[16][68];    // [k][n], stride 272B

    // ---- P0: zero cnt / cursor / C (idx exactly covers N_*B_) -----------
    if (idx < N_) { g_cnt[idx] = 0; g_cursor[idx] = 0; }
    g_C[idx] = 0.0f;

    gbar(gen0, 1);

    // ---- P1: degree histogram -------------------------------------------
    if (idx < E_) atomicAdd(&g_cnt[ei[E_ + idx]], 1);

    gbar(gen0, 2);

    // ---- P2: scan (block 0) + dis (blocks 1..4) -------------------------
    if (bid == 0) {
        int base = tid * 4;
        int v0 = g_cnt[base], v1 = g_cnt[base + 1], v2 = g_cnt[base + 2], v3 = g_cnt[base + 3];
        int tot = v0 + v1 + v2 + v3;
        s_scan[tid] = tot;
        __syncthreads();
        for (int off = 1; off < NTHR; off <<= 1) {
            int x = (tid >= off) ? s_scan[tid - off] : 0;
            __syncthreads();
            s_scan[tid] += x;
            __syncthreads();
        }
        int excl = s_scan[tid] - tot;
        g_offs[base + 0] = excl;
        g_offs[base + 1] = excl + v0;
        g_offs[base + 2] = excl + v0 + v1;
        g_offs[base + 3] = excl + v0 + v1 + v2;
        if (tid == NTHR - 1) g_offs[N_] = excl + tot;
    } else if (bid <= 4) {
        int i = (bid - 1) * NTHR + tid;
        float dv = rsqrtf((float)(g_cnt[i] + 1));   // +1 self-loop
        g_dis[i] = dv;
        g_C[i * B_ + (i >> 7)] = dv * dv;           // self-loop seed
    }

    gbar(gen0, 3);

    // ---- P3: scatter edges into CSR + C; node_mean ----------------------
    if (idx < E_) {
        int u = ei[idx];
        int v = ei[E_ + idx];
        float w = g_dis[u] * g_dis[v];
        int pos = g_offs[v] + atomicAdd(&g_cursor[v], 1);
        g_csr_src[pos] = u;
        g_csr_w[pos]   = w;
        atomicAdd(&g_C[u * B_ + (v >> 7)], w);
    }
    {   // node_mean: 32 nodes/block; lane = 16B chunk (64), sub = node slot (16)
        const int lane = tid & 63, sub = tid >> 6;
        const float inv = 1.0f / (float)P_;
#pragma unroll
        for (int r = 0; r < 2; r++) {
            int n = bid * 32 + r * 16 + sub;
            int b = n >> 7;
            int g = gids[n];
            const float4* base = (const float4*)(dge + ((size_t)(b * P_ * S_ + g)) * D_) + lane;
            float sx = 0, sy = 0, sz = 0, sw = 0;
#pragma unroll
            for (int h = 0; h < 2; h++) {        // 2 batches of 8 in flight
                float4 v[8];
#pragma unroll
                for (int p = 0; p < 8; p++) v[p] = base[(h * 8 + p) * (S_ * D_ / 4)];
#pragma unroll
                for (int p = 0; p < 8; p++) { sx += v[p].x; sy += v[p].y; sz += v[p].z; sw += v[p].w; }
            }
            float4 o; o.x = sx * inv; o.y = sy * inv; o.z = sz * inv; o.w = sw * inv;
            ((float4*)g_node_x)[n * (D_ / 4) + lane] = o;
        }
    }

    gbar(gen0, 4);

    // ---- P4: aggregate (gather over CSR); 4 groups x 8 nodes, no smem ---
    {
        const int group = tid >> 8;      // 0..3
        const int d = tid & 255;
#pragma unroll 1
        for (int vv = 0; vv < 8; vv++) {
            int v = bid * 32 + group * 8 + vv;
            int beg = g_offs[v], end = g_offs[v + 1];
            float dv = g_dis[v];
            float acc = dv * dv * g_node_x[v * D_ + d];
            float a0 = 0, a1 = 0, a2 = 0, a3 = 0, a4 = 0, a5 = 0, a6 = 0, a7 = 0;
            int i = beg;
            for (; i + 8 <= end; i += 8) {
                int u0 = g_csr_src[i + 0], u1 = g_csr_src[i + 1];
                int u2 = g_csr_src[i + 2], u3 = g_csr_src[i + 3];
                int u4 = g_csr_src[i + 4], u5 = g_csr_src[i + 5];
                int u6 = g_csr_src[i + 6], u7 = g_csr_src[i + 7];
                float w0 = g_csr_w[i + 0], w1 = g_csr_w[i + 1];
                float w2 = g_csr_w[i + 2], w3 = g_csr_w[i + 3];
                float w4 = g_csr_w[i + 4], w5 = g_csr_w[i + 5];
                float w6 = g_csr_w[i + 6], w7 = g_csr_w[i + 7];
                a0 += w0 * g_node_x[u0 * D_ + d];
                a1 += w1 * g_node_x[u1 * D_ + d];
                a2 += w2 * g_node_x[u2 * D_ + d];
                a3 += w3 * g_node_x[u3 * D_ + d];
                a4 += w4 * g_node_x[u4 * D_ + d];
                a5 += w5 * g_node_x[u5 * D_ + d];
                a6 += w6 * g_node_x[u6 * D_ + d];
                a7 += w7 * g_node_x[u7 * D_ + d];
            }
            for (; i < end; i++) a0 += g_csr_w[i] * g_node_x[g_csr_src[i] * D_ + d];
            acc += ((a0 + a1) + (a2 + a3)) + ((a4 + a5) + (a6 + a7));
            g_agg[v * D_ + d] = acc;
        }
    }

    gbar(gen0, 5);

    // ---- P5: x1 = relu(agg @ W1 + b1); 128x64 tile, 1024 thr, FFMA2 -----
    // pairing over N: acc[mi][npair], B pairs free via ulonglong2 of Bs
    {
        int m0 = (bid >> 2) * 128, n0 = (bid & 3) * 64;
        int tx = tid & 15, ty = tid >> 4;             // ty 0..63 -> 2 m rows
        unsigned long long acc[2][2];
        acc[0][0] = acc[0][1] = acc[1][0] = acc[1][1] = 0ull;

        for (int k0 = 0; k0 < 256; k0 += 16) {
            if (tid < 512) {   // A tile 128x16 -> As transposed
                int m = tid >> 2, kq = (tid & 3) << 2;
                float4 a = *(const float4*)&g_agg[(m0 + m) * 256 + k0 + kq];
                As[kq + 0][m] = a.x; As[kq + 1][m] = a.y;
                As[kq + 2][m] = a.z; As[kq + 3][m] = a.w;
            } else if (tid < 768) {   // B tile 16x64
                int t = tid - 512;
                int row = t >> 4, nq = (t & 15) << 2;
                *(float4*)&Bs[row][nq] = *(const float4*)&W1[(k0 + row) * 256 + n0 + nq];
            }
            __syncthreads();
#pragma unroll
            for (int kk = 0; kk < 16; kk++) {
                float2 av = *(const float2*)&As[kk][ty * 2];
                ulonglong2 bp = *(const ulonglong2*)&Bs[kk][tx * 4];
                unsigned long long a0 = pk2(av.x), a1 = pk2(av.y);
                acc[0][0] = ffma2(a0, bp.x, acc[0][0]);
                acc[0][1] = ffma2(a0, bp.y, acc[0][1]);
                acc[1][0] = ffma2(a1, bp.x, acc[1][0]);
                acc[1][1] = ffma2(a1, bp.y, acc[1][1]);
            }
            __syncthreads();
        }
        float bb[4];
#pragma unroll
        for (int j = 0; j < 4; j++) bb[j] = b1[n0 + tx * 4 + j];
#pragma unroll
        for (int mi = 0; mi < 2; mi++) {
            int m = m0 + ty * 2 + mi;
#pragma unroll
            for (int pi = 0; pi < 2; pi++) {
                float lo = __uint_as_float((unsigned)(acc[mi][pi] & 0xffffffffull));
                float hi = __uint_as_float((unsigned)(acc[mi][pi] >> 32));
                float2 o;
                o.x = fmaxf(lo + bb[pi * 2 + 0], 0.0f);
                o.y = fmaxf(hi + bb[pi * 2 + 1], 0.0f);
                *(float2*)&g_x1[m * 256 + n0 + tx * 4 + pi * 2] = o;
            }
        }
    }

    gbar(gen0, 6);

    // ---- P6: pool partials: 4 quarters x 8 u-rows -----------------------
    {
        int u0 = bid * 32;
        for (int i = tid; i < 32 * 32; i += NTHR) sC[i >> 5][i & 31] = g_C[u0 * 32 + i];
        __syncthreads();
        int quarter = tid >> 8, d = tid & 255;
        float pacc[32];
#pragma unroll
        for (int b = 0; b < 32; b++) pacc[b] = 0.0f;
        for (int uu = 0; uu < 8; uu++) {
            int us = quarter * 8 + uu;
            float x = g_x1[(u0 + us) * 256 + d];
#pragma unroll
            for (int b = 0; b < 32; b++) pacc[b] += sC[us][b] * x;
        }
        int slot = bid * 4 + quarter;
#pragma unroll
        for (int b = 0; b < 32; b++) g_part[slot * (B_ * H_) + b * 256 + d] = pacc[b];
    }

    gbar(gen0, 7);

    // ---- P7: reduce 512 partial slots -> tmp (16 threads per output) ----
    {
        int oid = idx >> 4;          // 0..8191
        int part = idx & 15;
        float s = 0.0f;
        int k0 = part * 32;
#pragma unroll 8
        for (int k = 0; k < 32; k++) s += g_part[(k0 + k) * (B_ * H_) + oid];
        s += __shfl_xor_sync(0xffffffffu, s, 1);
        s += __shfl_xor_sync(0xffffffffu, s, 2);
        s += __shfl_xor_sync(0xffffffffu, s, 4);
        s += __shfl_xor_sync(0xffffffffu, s, 8);
        if (part == 0) g_tmp[oid] = s;
    }

    gbar(gen0, 8);

    // ---- P8: out = tmp @ W2 / NG + b2 (16 threads per output) -----------
    {
        int oid = idx >> 4;          // 0..8191
        int part = idx & 15;
        int b = oid >> 8, h = oid & 255;
        const float* tr = g_tmp + b * 256 + part * 16;
        const float* w2 = W2 + (part * 16) * 256 + h;
        float acc = 0.0f;
#pragma unroll 8
        for (int d = 0; d < 16; d++) acc += tr[d] * w2[d * 256];
        acc += __shfl_xor_sync(0xffffffffu, acc, 1);
        acc += __shfl_xor_sync(0xffffffffu, acc, 2);
        acc += __shfl_xor_sync(0xffffffffu, acc, 4);
        acc += __shfl_xor_sync(0xffffffffu, acc, 8);
        if (part == 0) out[oid] = acc * (1.0f / NG_) + b2[h];
    }
}

// ---------------- launch -----------------------------------------------------
extern "C" void kernel_launch(void* const* d_in, const int* in_sizes, int n_in,
                              void* d_out, int out_size) {
    const float* dge  = (const float*)d_in[0];
    const int*   gids = (const int*)  d_in[1];
    const int*   ei   = (const int*)  d_in[2];
    const float* W1   = (const float*)d_in[3];
    const float* b1   = (const float*)d_in[4];
    const float* W2   = (const float*)d_in[5];
    const float* b2   = (const float*)d_in[6];
    float* out = (float*)d_out;

    fused_kernel<<<NBLK, NTHR>>>(dge, gids, ei, W1, b1, W2, b2, out);
}